// round 7
// baseline (speedup 1.0000x reference)
#include <cuda_runtime.h>

// Depthwise conv_transpose2d(stride=4, k=7, bilinear) == separable x4 upsample.
// Input  x: [4, 256, 64, 64] fp32, Output: [4, 256, 259, 259] fp32.
//
// Tap algebra (p = o & 3, cell = o >> 2):
//   out[o] = wA * in[cell-1] + (1-wA) * in[cell],  wA = 0.75 - 0.25*p
// (p=3 -> pure in[cell]; OOB taps = 0.)
//
// One block per plane (grid=1024), 288 threads. Phase 1: cooperatively stage
// the whole 16KB input plane into smem with 1024 parallel LDG.128 (removes
// all global-load latency from the main loop). Phase 2: thread = one output
// column ox, rolling over 65 y-blocks; per iteration 2 LDS (row a+1 taps,
// broadcast-friendly) + 4 coalesced row stores. Stores are fire-and-forget,
// so the warp never waits on memory inside the loop.

namespace {
constexpr int H = 64, W = 64;
constexpr int OH = 259, OW = 259;
constexpr int PLANES = 4 * 256;     // 1024
constexpr int THREADS = 288;        // 9 warps, covers ox 0..258
constexpr int PLANE_F4 = H * W / 4; // 1024 float4 per plane
}

__global__ void __launch_bounds__(THREADS)
bilinear_up4_smemin_kernel(const float* __restrict__ x, float* __restrict__ out) {
    __shared__ float4 sx4[PLANE_F4];                 // 16KB input plane
    float* sx = reinterpret_cast<float*>(sx4);

    int tid   = threadIdx.x;
    int plane = blockIdx.x;

    // ---- phase 1: stage input plane (fully parallel, MLP ~4/thread) ----
    const float4* __restrict__ xp4 =
        reinterpret_cast<const float4*>(x + plane * (H * W));
#pragma unroll
    for (int i = tid; i < PLANE_F4; i += THREADS)
        sx4[i] = __ldg(xp4 + i);
    __syncthreads();

    if (tid >= OW) return;
    int ox = tid;

    int b  = ox >> 2;
    int px = ox & 3;
    float wxA = 0.75f - 0.25f * (float)px;           // weight on col b-1
    bool cAok = (b >= 1);
    bool cBok = (b < W);                             // b==64 only at ox==258

    float* __restrict__ op = out + (size_t)plane * ((size_t)OH * OW) + ox;

    // h(row -1) = 0; blend row 0.
    float v0 = cAok ? sx[b - 1] : 0.0f;
    float v1 = cBok ? sx[b]     : 0.0f;
    float hPrev = 0.0f;
    float hCur  = fmaf(wxA, v0 - v1, v1);

#pragma unroll 1
    for (int a = 0; a <= 64; a++) {
        // next input row taps from smem (no scoreboard exposure)
        float n0 = 0.0f, n1 = 0.0f;
        int r = a + 1;
        if (r < H) {
            const float* row = sx + r * W;
            n0 = cAok ? row[b - 1] : 0.0f;
            n1 = cBok ? row[b]     : 0.0f;
        }

        // 4 output rows of y-block a (coalesced across the warp)
        float dh = hPrev - hCur;
        float* o0 = op + (size_t)(4 * a) * OW;
        o0[0]      = fmaf(0.75f, dh, hCur);
        o0[OW]     = fmaf(0.50f, dh, hCur);
        o0[2 * OW] = fmaf(0.25f, dh, hCur);
        if (a < 64)
            o0[3 * OW] = hCur;                       // oy = 4a+3

        hPrev = hCur;
        hCur  = fmaf(wxA, n0 - n1, n1);
    }
}

extern "C" void kernel_launch(void* const* d_in, const int* in_sizes, int n_in,
                              void* d_out, int out_size) {
    const float* x = (const float*)d_in[0];
    float* out = (float*)d_out;
    (void)in_sizes; (void)n_in; (void)out_size;

    bilinear_up4_smemin_kernel<<<PLANES, THREADS>>>(x, out);
}

// round 8
// speedup vs baseline: 1.5219x; 1.5219x over previous
#include <cuda_runtime.h>

// Depthwise conv_transpose2d(stride=4, k=7, bilinear) == separable x4 upsample.
// Input  x: [4, 256, 64, 64] fp32, Output: [4, 256, 259, 259] fp32.
//
// Tap algebra (p = o & 3, cell = o >> 2):
//   out[o] = wA * in[cell-1] + (1-wA) * in[cell],  wA = 0.75 - 0.25*p
// (p=3 -> pure in[cell]; OOB taps = 0.)
//
// R5 rolling kernel + (a) 2-deep load pipeline: rows a+1 AND a+2 in flight,
// so a row's taps are issued ~2 iteration bodies before use (covers L2
// latency; this was R5's binding stall), and (b) 5 stripes of 13 y-blocks
// per plane (grid 5x1024) for wave balance. Store pattern unchanged
// (warp-coalesced scalar rows -- proven optimal in R3/R6).

namespace {
constexpr int H = 64, W = 64;
constexpr int OH = 259, OW = 259;
constexpr int PLANES = 4 * 256;     // 1024
constexpr int THREADS = 288;        // 9 warps, covers ox 0..258
constexpr int STRIPE = 13;          // y-blocks per block; 5*13 = 65
constexpr int NSTRIPES = 5;
}

__global__ void __launch_bounds__(THREADS)
bilinear_up4_pipe_kernel(const float* __restrict__ x, float* __restrict__ out) {
    int ox = threadIdx.x;
    if (ox >= OW) return;
    int stripe = blockIdx.x;
    int plane  = blockIdx.y;
    int a0 = stripe * STRIPE;

    const float* __restrict__ xp = x + plane * (H * W);
    float* __restrict__ op = out + (size_t)plane * ((size_t)OH * OW) + ox;

    int b  = ox >> 2;
    int px = ox & 3;
    float wxA = 0.75f - 0.25f * (float)px;   // weight on col b-1 (0 at px==3)
    bool cAok = (b >= 1);
    bool cBok = (b < W);                     // b==64 only at ox==258

    // tap loader for input row r (OOB -> 0)
    auto taps = [&](int r, float& t0, float& t1) {
        t0 = 0.0f; t1 = 0.0f;
        if ((unsigned)r < (unsigned)H) {
            const float* row = xp + r * W;
            t0 = cAok ? __ldg(row + b - 1) : 0.0f;
            t1 = cBok ? __ldg(row + b)     : 0.0f;
        }
    };

    // preamble: h(a0-1), h(a0), and row a0+1 in flight
    float p0, p1, q0, q1, f0, f1;
    taps(a0 - 1, p0, p1);
    taps(a0,     q0, q1);
    taps(a0 + 1, f0, f1);
    float hPrev = fmaf(wxA, p0 - p1, p1);
    float hCur  = fmaf(wxA, q0 - q1, q1);

#pragma unroll 1
    for (int a = a0; a < a0 + STRIPE; a++) {
        // issue row a+2 immediately (consumed ~2 bodies later)
        float g0, g1;
        taps(a + 2, g0, g1);

        // 4 output rows of y-block a (coalesced across the warp)
        float dh = hPrev - hCur;
        float* o0 = op + (size_t)(4 * a) * OW;
        o0[0]      = fmaf(0.75f, dh, hCur);
        o0[OW]     = fmaf(0.50f, dh, hCur);
        o0[2 * OW] = fmaf(0.25f, dh, hCur);
        if (a < 64)
            o0[3 * OW] = hCur;               // oy = 4a+3 (only while < 259)

        // rotate pipeline: consume row a+1, keep a+2 in flight
        hPrev = hCur;
        hCur  = fmaf(wxA, f0 - f1, f1);
        f0 = g0; f1 = g1;
    }
}

extern "C" void kernel_launch(void* const* d_in, const int* in_sizes, int n_in,
                              void* d_out, int out_size) {
    const float* x = (const float*)d_in[0];
    float* out = (float*)d_out;
    (void)in_sizes; (void)n_in; (void)out_size;

    dim3 grid(NSTRIPES, PLANES);             // 5 x 1024 = 5120 blocks
    bilinear_up4_pipe_kernel<<<grid, THREADS>>>(x, out);
}

// round 9
// speedup vs baseline: 1.6301x; 1.0711x over previous
#include <cuda_runtime.h>

// Depthwise conv_transpose2d(stride=4, k=7, bilinear) == separable x4 upsample.
// Input  x: [4, 256, 64, 64] fp32, Output: [4, 256, 259, 259] fp32.
//
// out[o] = wA*in[cell-1] + (1-wA)*in[cell], wA = 0.75-0.25*(o&3), OOB taps = 0.
//
// KEY FACT: the row alignment phase hds(oy) = (oy - plane) & 3 satisfies
// hds(4a+py) = (py - plane) & 3  -- constant per (plane, py). So each output
// row decomposes STATICALLY into hds head scalars + 64 aligned float4 chunks
// + (3-hds) tail scalars. We specialize on plane&3 (uniform per block), so
// all weights/cell choices are compile-time and every chunk store is an
// aligned STG.128 (1 L1 wavefront per warp-store, minimal issue cost).
//
// Block = 256 threads = 4 groups of 64; group g owns y-blocks [b0,b1) of its
// plane; thread j owns chunk j (cells j-1, j, j+1) and rolls vertically with
// a 2-deep row pipeline (A=row a-1, B=row a, N=row a+1, P=row a+2 in flight).
// Threads 0 / 63 additionally emit the 3 edge scalars per row.

namespace {
constexpr int H = 64, W = 64;
constexpr int OH = 259, OW = 259;
constexpr int PLANES = 4 * 256;   // 1024
}

template <int PM>   // plane & 3
__device__ __forceinline__ void run_group(
    const float* __restrict__ xp, float* __restrict__ op,
    int j, int b0, int b1)
{
    const bool c0ok = (j >= 1);
    const bool c2ok = (j < 63);

    auto load3 = [&](int r, float& t0, float& t1, float& t2) {
        t0 = 0.f; t1 = 0.f; t2 = 0.f;
        if ((unsigned)r < (unsigned)H) {
            const float* row = xp + r * W;
            t0 = c0ok ? __ldg(row + j - 1) : 0.f;
            t1 = __ldg(row + j);
            t2 = c2ok ? __ldg(row + j + 1) : 0.f;
        }
    };

    // One output row: vertical blend (weight wy on row A), then the static
    // hds-pattern horizontal blend + aligned float4 store + edge scalars.
    auto doRow = [&](float* rowOut, float wy, int hds,
                     float dA0, float dA1, float dA2,
                     float B0, float B1, float B2) {
        float v0 = fmaf(wy, dA0, B0);
        float v1 = fmaf(wy, dA1, B1);
        float v2 = fmaf(wy, dA2, B2);
        float d0 = v0 - v1, d1 = v1 - v2;
        float4 o;
        if (hds == 0)
            o = make_float4(fmaf(0.75f,d0,v1), fmaf(0.50f,d0,v1), fmaf(0.25f,d0,v1), v1);
        else if (hds == 1)
            o = make_float4(fmaf(0.50f,d0,v1), fmaf(0.25f,d0,v1), v1, fmaf(0.75f,d1,v2));
        else if (hds == 2)
            o = make_float4(fmaf(0.25f,d0,v1), v1, fmaf(0.75f,d1,v2), fmaf(0.50f,d1,v2));
        else
            o = make_float4(v1, fmaf(0.75f,d1,v2), fmaf(0.50f,d1,v2), fmaf(0.25f,d1,v2));
        *reinterpret_cast<float4*>(rowOut + hds + 4 * j) = o;

        if (j == 0) {            // head scalars ox = 0..hds-1 (cells -1,0; cell -1 = 0)
#pragma unroll
            for (int s = 0; s < 3; s++)
                if (s < hds) rowOut[s] = fmaf(0.75f - 0.25f * s, d0, v1);
        } else if (j == 63) {    // tail scalars ox = 256+u, u = hds..2 (cells 63,64; 64 = 0)
#pragma unroll
            for (int u = 0; u < 3; u++)
                if (u >= hds) rowOut[256 + u] = fmaf(0.75f - 0.25f * u, d1, v2);
        }
    };

    constexpr int h0 = (0 - PM) & 3, h1 = (1 - PM) & 3;
    constexpr int h2 = (2 - PM) & 3, h3 = (3 - PM) & 3;

    float A0,A1,A2, B0,B1,B2, N0,N1,N2;
    load3(b0 - 1, A0, A1, A2);
    load3(b0,     B0, B1, B2);
    load3(b0 + 1, N0, N1, N2);

#pragma unroll 1
    for (int a = b0; a < b1; a++) {
        float P0, P1, P2;
        load3(a + 2, P0, P1, P2);            // consumed 2 blocks later
        float dA0 = A0 - B0, dA1 = A1 - B1, dA2 = A2 - B2;
        float* r0 = op + (size_t)(4 * a) * OW;
        doRow(r0,          0.75f, h0, dA0, dA1, dA2, B0, B1, B2);
        doRow(r0 + OW,     0.50f, h1, dA0, dA1, dA2, B0, B1, B2);
        doRow(r0 + 2 * OW, 0.25f, h2, dA0, dA1, dA2, B0, B1, B2);
        if (a < 64)
            doRow(r0 + 3 * OW, 0.0f, h3, dA0, dA1, dA2, B0, B1, B2);
        A0 = B0; A1 = B1; A2 = B2;
        B0 = N0; B1 = N1; B2 = N2;
        N0 = P0; N1 = P1; N2 = P2;
    }
}

__global__ void __launch_bounds__(256, 7)
bilinear_up4_chunk_kernel(const float* __restrict__ x, float* __restrict__ out) {
    int tid = threadIdx.x;
    int g = tid >> 6;                  // group 0..3 (y-stripe)
    int j = tid & 63;                  // chunk / cell index
    int plane = blockIdx.x;

    const float* xp = x + plane * (H * W);
    float* op = out + (size_t)plane * ((size_t)OH * OW);

    // y-block ranges per group: {0..16, 17..32, 33..48, 49..64}
    int b0 = (g == 0) ? 0 : (g == 1) ? 17 : (g == 2) ? 33 : 49;
    int b1 = (g == 0) ? 17 : (g == 1) ? 33 : (g == 2) ? 49 : 65;

    switch (plane & 3) {
        case 0:  run_group<0>(xp, op, j, b0, b1); break;
        case 1:  run_group<1>(xp, op, j, b0, b1); break;
        case 2:  run_group<2>(xp, op, j, b0, b1); break;
        default: run_group<3>(xp, op, j, b0, b1); break;
    }
}

extern "C" void kernel_launch(void* const* d_in, const int* in_sizes, int n_in,
                              void* d_out, int out_size) {
    const float* x = (const float*)d_in[0];
    float* out = (float*)d_out;
    (void)in_sizes; (void)n_in; (void)out_size;

    bilinear_up4_chunk_kernel<<<PLANES, 256>>>(x, out);
}

// round 10
// speedup vs baseline: 1.6965x; 1.0407x over previous
#include <cuda_runtime.h>

// Depthwise conv_transpose2d(stride=4, k=7, bilinear) == separable x4 upsample.
// Input  x: [4, 256, 64, 64] fp32, Output: [4, 256, 259, 259] fp32.
//
// out[o] = wA*in[cell-1] + (1-wA)*in[cell], wA = 0.75-0.25*(o&3), OOB taps = 0.
//
// Row alignment phase hds(4a+py) = (py - plane) & 3 is constant per
// (plane, py): each output row = hds head scalars + 64 aligned float4
// chunks + (3-hds) tail scalars, all decided at compile time via the
// plane&3 template. Every chunk store is an aligned STG.128.
//
// R10 change vs R9: scheduling granularity. Each (plane, y-group) is its
// own 64-thread block (grid 4 x 1024 = 4096 blocks, 27.7/SM) instead of
// 4 groups fused into 256-thread blocks (1024 blocks, 6.9/SM wave
// quantization -> occ 62%). Kernel body identical.
//
// Thread j owns chunk j (input cells j-1, j, j+1) and rolls vertically
// over its group's y-blocks with a 2-deep row pipeline (rows a+1, a+2 in
// flight). Threads 0 / 63 emit the 3 edge scalars per row.

namespace {
constexpr int H = 64, W = 64;
constexpr int OH = 259, OW = 259;
constexpr int PLANES = 4 * 256;   // 1024
}

template <int PM>   // plane & 3
__device__ __forceinline__ void run_group(
    const float* __restrict__ xp, float* __restrict__ op,
    int j, int b0, int b1)
{
    const bool c0ok = (j >= 1);
    const bool c2ok = (j < 63);

    auto load3 = [&](int r, float& t0, float& t1, float& t2) {
        t0 = 0.f; t1 = 0.f; t2 = 0.f;
        if ((unsigned)r < (unsigned)H) {
            const float* row = xp + r * W;
            t0 = c0ok ? __ldg(row + j - 1) : 0.f;
            t1 = __ldg(row + j);
            t2 = c2ok ? __ldg(row + j + 1) : 0.f;
        }
    };

    auto doRow = [&](float* rowOut, float wy, int hds,
                     float dA0, float dA1, float dA2,
                     float B0, float B1, float B2) {
        float v0 = fmaf(wy, dA0, B0);
        float v1 = fmaf(wy, dA1, B1);
        float v2 = fmaf(wy, dA2, B2);
        float d0 = v0 - v1, d1 = v1 - v2;
        float4 o;
        if (hds == 0)
            o = make_float4(fmaf(0.75f,d0,v1), fmaf(0.50f,d0,v1), fmaf(0.25f,d0,v1), v1);
        else if (hds == 1)
            o = make_float4(fmaf(0.50f,d0,v1), fmaf(0.25f,d0,v1), v1, fmaf(0.75f,d1,v2));
        else if (hds == 2)
            o = make_float4(fmaf(0.25f,d0,v1), v1, fmaf(0.75f,d1,v2), fmaf(0.50f,d1,v2));
        else
            o = make_float4(v1, fmaf(0.75f,d1,v2), fmaf(0.50f,d1,v2), fmaf(0.25f,d1,v2));
        *reinterpret_cast<float4*>(rowOut + hds + 4 * j) = o;

        if (j == 0) {            // head scalars ox = 0..hds-1
#pragma unroll
            for (int s = 0; s < 3; s++)
                if (s < hds) rowOut[s] = fmaf(0.75f - 0.25f * s, d0, v1);
        } else if (j == 63) {    // tail scalars ox = 256+u, u = hds..2
#pragma unroll
            for (int u = 0; u < 3; u++)
                if (u >= hds) rowOut[256 + u] = fmaf(0.75f - 0.25f * u, d1, v2);
        }
    };

    constexpr int h0 = (0 - PM) & 3, h1 = (1 - PM) & 3;
    constexpr int h2 = (2 - PM) & 3, h3 = (3 - PM) & 3;

    float A0,A1,A2, B0,B1,B2, N0,N1,N2;
    load3(b0 - 1, A0, A1, A2);
    load3(b0,     B0, B1, B2);
    load3(b0 + 1, N0, N1, N2);

#pragma unroll 1
    for (int a = b0; a < b1; a++) {
        float P0, P1, P2;
        load3(a + 2, P0, P1, P2);            // consumed 2 blocks later
        float dA0 = A0 - B0, dA1 = A1 - B1, dA2 = A2 - B2;
        float* r0 = op + (size_t)(4 * a) * OW;
        doRow(r0,          0.75f, h0, dA0, dA1, dA2, B0, B1, B2);
        doRow(r0 + OW,     0.50f, h1, dA0, dA1, dA2, B0, B1, B2);
        doRow(r0 + 2 * OW, 0.25f, h2, dA0, dA1, dA2, B0, B1, B2);
        if (a < 64)
            doRow(r0 + 3 * OW, 0.0f, h3, dA0, dA1, dA2, B0, B1, B2);
        A0 = B0; A1 = B1; A2 = B2;
        B0 = N0; B1 = N1; B2 = N2;
        N0 = P0; N1 = P1; N2 = P2;
    }
}

__global__ void __launch_bounds__(64)
bilinear_up4_chunk64_kernel(const float* __restrict__ x, float* __restrict__ out) {
    int j = threadIdx.x;               // chunk / cell index 0..63
    int g = blockIdx.x;                // y-group 0..3
    int plane = blockIdx.y;

    const float* xp = x + plane * (H * W);
    float* op = out + (size_t)plane * ((size_t)OH * OW);

    // y-block ranges per group: {0..16, 17..32, 33..48, 49..64}
    int b0 = (g == 0) ? 0 : (g == 1) ? 17 : (g == 2) ? 33 : 49;
    int b1 = (g == 0) ? 17 : (g == 1) ? 33 : (g == 2) ? 49 : 65;

    switch (plane & 3) {
        case 0:  run_group<0>(xp, op, j, b0, b1); break;
        case 1:  run_group<1>(xp, op, j, b0, b1); break;
        case 2:  run_group<2>(xp, op, j, b0, b1); break;
        default: run_group<3>(xp, op, j, b0, b1); break;
    }
}

extern "C" void kernel_launch(void* const* d_in, const int* in_sizes, int n_in,
                              void* d_out, int out_size) {
    const float* x = (const float*)d_in[0];
    float* out = (float*)d_out;
    (void)in_sizes; (void)n_in; (void)out_size;

    dim3 grid(4, PLANES);              // 4096 blocks x 64 threads
    bilinear_up4_chunk64_kernel<<<grid, 64>>>(x, out);
}